// round 11
// baseline (speedup 1.0000x reference)
#include <cuda_runtime.h>
#include <cuda_bf16.h>
#include <cstdint>
#include <cstddef>

// Problem constants
#define TT   2048
#define HH   1024
#define EE   1024
#define VV   32000
#define G4   4096
#define NCTA 128
#define UPC  8

// ---------------- scratch (no allocations allowed) ----------------
__device__ float g_xg[(size_t)TT * G4];                       // [T,4H] fp32
__device__ float g_scores[(size_t)TT * VV];                   // [T,V] fp32
__device__ __align__(16) __nv_bfloat16 g_x16[(size_t)TT * EE];
__device__ __align__(16) __nv_bfloat16 g_wih16[(size_t)G4 * EE];
__device__ __align__(16) __nv_bfloat16 g_wout16[(size_t)VV * HH];
__device__ __align__(16) __nv_bfloat16 g_hs16[(size_t)TT * HH];
__device__ float g_hbuf[2][HH];
__device__ unsigned g_arrive;    // monotonic counters (R2-proven, replay-safe)
__device__ unsigned g_release;

// ---------------- sync primitives ----------------
__device__ __forceinline__ unsigned atom_add_acqrel(unsigned* p, unsigned v) {
    unsigned old;
    asm volatile("atom.acq_rel.gpu.global.add.u32 %0, [%1], %2;"
                 : "=r"(old) : "l"(p), "r"(v) : "memory");
    return old;
}
__device__ __forceinline__ unsigned atom_add_release(unsigned* p, unsigned v) {
    unsigned old;
    asm volatile("atom.release.gpu.global.add.u32 %0, [%1], %2;"
                 : "=r"(old) : "l"(p), "r"(v) : "memory");
    return old;
}
__device__ __forceinline__ unsigned ld_acquire(const unsigned* p) {
    unsigned v;
    asm volatile("ld.acquire.gpu.global.u32 %0, [%1];" : "=r"(v) : "l"(p) : "memory");
    return v;
}

// ---------------- conversions ----------------
__global__ void gather_x16_kernel(const int* __restrict__ seq,
                                  const float* __restrict__ emb)
{
    int t = blockIdx.x;
    const float4* src = (const float4*)(emb + (size_t)seq[t] * EE);
    uint2* dst = (uint2*)(g_x16 + (size_t)t * EE);
    int i = threadIdx.x;            // 256 threads, EE/4 = 256 float4
    float4 v = src[i];
    __nv_bfloat162 a = __floats2bfloat162_rn(v.x, v.y);
    __nv_bfloat162 b = __floats2bfloat162_rn(v.z, v.w);
    dst[i] = make_uint2(*(unsigned*)&a, *(unsigned*)&b);
}

__global__ void f2bf4_kernel(const float4* __restrict__ src,
                             uint2* __restrict__ dst, size_t n4)
{
    size_t i = (size_t)blockIdx.x * blockDim.x + threadIdx.x;
    size_t stride = (size_t)gridDim.x * blockDim.x;
    for (; i < n4; i += stride) {
        float4 v = src[i];
        __nv_bfloat162 a = __floats2bfloat162_rn(v.x, v.y);
        __nv_bfloat162 b = __floats2bfloat162_rn(v.z, v.w);
        dst[i] = make_uint2(*(unsigned*)&a, *(unsigned*)&b);
    }
}

// =================================================================
// bf16 tensor-core GEMM — same tile/mma structure as the proven
// version, load path switched to a 3-stage cp.async pipeline.
// Dynamic smem: 3 stages x (A+B) x 128 x SKP bf16 = 61,440 B.
// =================================================================
#define SKP 40
#define STG 3
#define STAGE_ELEMS (128 * SKP)

__device__ __forceinline__ void cp16(void* smem, const void* gmem) {
    uint32_t s = (uint32_t)__cvta_generic_to_shared(smem);
    asm volatile("cp.async.cg.shared.global [%0], [%1], 16;" :: "r"(s), "l"(gmem));
}

__device__ __forceinline__ void ldsm_x4(uint32_t& r0, uint32_t& r1,
                                        uint32_t& r2, uint32_t& r3,
                                        const __nv_bfloat16* p)
{
    uint32_t addr = (uint32_t)__cvta_generic_to_shared(p);
    asm volatile("ldmatrix.sync.aligned.m8n8.x4.shared.b16 {%0,%1,%2,%3}, [%4];\n"
                 : "=r"(r0), "=r"(r1), "=r"(r2), "=r"(r3) : "r"(addr));
}

__device__ __forceinline__ void mma16816(float* d, const uint32_t* a,
                                         const uint32_t* b)
{
    asm volatile(
        "mma.sync.aligned.m16n8k16.row.col.f32.bf16.bf16.f32 "
        "{%0,%1,%2,%3}, {%4,%5,%6,%7}, {%8,%9}, {%0,%1,%2,%3};\n"
        : "+f"(d[0]), "+f"(d[1]), "+f"(d[2]), "+f"(d[3])
        : "r"(a[0]), "r"(a[1]), "r"(a[2]), "r"(a[3]), "r"(b[0]), "r"(b[1]));
}

__global__ void __launch_bounds__(256) bgemm_tn(
    const __nv_bfloat16* __restrict__ A, const __nv_bfloat16* __restrict__ B,
    const float* __restrict__ bias1, const float* __restrict__ bias2,
    float* __restrict__ C, int M, int N, int K)
{
    extern __shared__ __nv_bfloat16 smp[];
    __nv_bfloat16* Asm = smp;                     // [STG][STAGE_ELEMS]
    __nv_bfloat16* Bsm = smp + STG * STAGE_ELEMS;

    const int tid = threadIdx.x;
    const int lane = tid & 31;
    const int w = tid >> 5;
    const int wm = w >> 2;
    const int wn = w & 3;
    const int bm = blockIdx.y * 128, bn = blockIdx.x * 128;

    const int c0 = tid, c1 = tid + 256;
    const int r0g = c0 >> 2, k0g = (c0 & 3) * 8;
    const int r1g = c1 >> 2, k1g = (c1 & 3) * 8;
    const __nv_bfloat16* Ap0 = A + (size_t)(bm + r0g) * K + k0g;
    const __nv_bfloat16* Ap1 = A + (size_t)(bm + r1g) * K + k1g;
    const __nv_bfloat16* Bp0 = B + (size_t)(bn + r0g) * K + k0g;
    const __nv_bfloat16* Bp1 = B + (size_t)(bn + r1g) * K + k1g;

    const int so0 = r0g * SKP + k0g;   // smem element offsets (16B aligned)
    const int so1 = r1g * SKP + k1g;

    float acc[4][4][4];
#pragma unroll
    for (int i = 0; i < 4; ++i)
#pragma unroll
        for (int j = 0; j < 4; ++j)
#pragma unroll
            for (int q = 0; q < 4; ++q) acc[i][j][q] = 0.f;

    const int KT = K / 32;

    // prologue: stages 0 and 1 in flight
#pragma unroll
    for (int s = 0; s < STG - 1; ++s) {
        int ko = s * 32;
        __nv_bfloat16* As = Asm + s * STAGE_ELEMS;
        __nv_bfloat16* Bs = Bsm + s * STAGE_ELEMS;
        cp16(As + so0, Ap0 + ko);
        cp16(As + so1, Ap1 + ko);
        cp16(Bs + so0, Bp0 + ko);
        cp16(Bs + so1, Bp1 + ko);
        asm volatile("cp.async.commit_group;" ::: "memory");
    }

    for (int kt = 0; kt < KT; ++kt) {
        asm volatile("cp.async.wait_group %0;" :: "n"(STG - 2) : "memory");
        __syncthreads();

        const int slot = kt % STG;
        const __nv_bfloat16* As = Asm + slot * STAGE_ELEMS;
        const __nv_bfloat16* Bs = Bsm + slot * STAGE_ELEMS;
#pragma unroll
        for (int ks = 0; ks < 2; ++ks) {
            uint32_t af[4][4];
#pragma unroll
            for (int mf = 0; mf < 4; ++mf)
                ldsm_x4(af[mf][0], af[mf][1], af[mf][2], af[mf][3],
                        &As[(wm * 64 + mf * 16 + (lane & 15)) * SKP
                            + ks * 16 + (lane >> 4) * 8]);
            uint32_t bf[4][2];
#pragma unroll
            for (int p = 0; p < 2; ++p) {
                uint32_t r0, r1, r2, r3;
                ldsm_x4(r0, r1, r2, r3,
                        &Bs[(wn * 32 + p * 16 + ((lane >> 4) << 3) + (lane & 7)) * SKP
                            + ks * 16 + ((lane >> 3) & 1) * 8]);
                bf[p * 2][0] = r0; bf[p * 2][1] = r1;
                bf[p * 2 + 1][0] = r2; bf[p * 2 + 1][1] = r3;
            }
#pragma unroll
            for (int mf = 0; mf < 4; ++mf)
#pragma unroll
                for (int nf = 0; nf < 4; ++nf)
                    mma16816(acc[mf][nf], af[mf], bf[nf]);
        }

        // issue stage kt+STG-1 into slot (kt-1)%STG (all warps are past
        // the top-of-iter syncthreads, so that slot's compute is done)
        int ktn = kt + STG - 1;
        if (ktn < KT) {
            int ko = ktn * 32;
            int ns = ktn % STG;
            __nv_bfloat16* Aw = Asm + ns * STAGE_ELEMS;
            __nv_bfloat16* Bw = Bsm + ns * STAGE_ELEMS;
            cp16(Aw + so0, Ap0 + ko);
            cp16(Aw + so1, Ap1 + ko);
            cp16(Bw + so0, Bp0 + ko);
            cp16(Bw + so1, Bp1 + ko);
        }
        asm volatile("cp.async.commit_group;" ::: "memory"); // keep group count in lockstep
    }

    const int gid = lane >> 2, tg = lane & 3;
#pragma unroll
    for (int mf = 0; mf < 4; ++mf) {
        int row0 = bm + wm * 64 + mf * 16 + gid;
#pragma unroll
        for (int nf = 0; nf < 4; ++nf) {
            int col = bn + wn * 32 + nf * 8 + tg * 2;
            float b0 = 0.f, b1 = 0.f;
            if (bias1) { b0 += bias1[col]; b1 += bias1[col + 1]; }
            if (bias2) { b0 += bias2[col]; b1 += bias2[col + 1]; }
            C[(size_t)row0 * N + col]           = acc[mf][nf][0] + b0;
            C[(size_t)row0 * N + col + 1]       = acc[mf][nf][1] + b1;
            C[(size_t)(row0 + 8) * N + col]     = acc[mf][nf][2] + b0;
            C[(size_t)(row0 + 8) * N + col + 1] = acc[mf][nf][3] + b1;
        }
    }
}
#define BGEMM_SMEM (STG * STAGE_ELEMS * 2 * (int)sizeof(__nv_bfloat16))

// =================================================================
// Persistent LSTM scan.
// Barrier: R2 topology (measured fastest of 5 variants), with the
// __threadfence replaced by release/acquire semantics on the barrier
// ops themselves (standard grid.sync pattern):
//   __syncthreads -> tid0 atom.add.ACQ_REL(g_arrive);
//   128th arriver atom.add.RELEASE(g_release);
//   other tid0's ld.ACQUIRE-poll g_release; __syncthreads.
// Next step's xg prefetched BEFORE the barrier so its L2 latency
// hides behind the poll. Parallel activations on lanes 0-3; hs16
// bookkeeping on lane 1.
// =================================================================
__global__ void __launch_bounds__(256, 1) lstm_scan_kernel(
    const float* __restrict__ h0, const float* __restrict__ c0,
    const float* __restrict__ W_hh, float* __restrict__ out_tail)
{
    __shared__ float sh[HH];
    const int tid  = threadIdx.x;
    const int lane = tid & 31;
    const int w    = tid >> 5;
    const int j    = blockIdx.x * UPC + w;

    float4 wreg[4][8];
#pragma unroll
    for (int g = 0; g < 4; ++g)
#pragma unroll
        for (int i = 0; i < 8; ++i)
            wreg[g][i] = *(const float4*)(W_hh + (size_t)(g * HH + j) * HH
                                          + lane * 4 + 128 * i);

    float c_reg = c0[j];
    const unsigned relbase = *(volatile unsigned*)&g_release; // before 1st arrive

    float xgv = 0.f;                 // xg prefetch register (lanes 0-3)
    if (lane < 4)
        xgv = __ldcg(&g_xg[0 * G4 + lane * HH + j]);

    for (int t = 0; t < TT; ++t) {
        const float* hsrc = (t == 0) ? h0 : g_hbuf[t & 1];
        float4 hv = __ldcg((const float4*)hsrc + tid);
        *((float4*)sh + tid) = hv;
        __syncthreads();

        float4 hreg[8];
#pragma unroll
        for (int i = 0; i < 8; ++i)
            hreg[i] = *((const float4*)sh + lane + 32 * i);

        float gate[4];
#pragma unroll
        for (int g = 0; g < 4; ++g) {
            float s0 = 0.f, s1 = 0.f;        // 2 accumulators: halve FFMA chain
#pragma unroll
            for (int i = 0; i < 4; ++i) {
                s0 += wreg[g][i].x * hreg[i].x + wreg[g][i].y * hreg[i].y
                    + wreg[g][i].z * hreg[i].z + wreg[g][i].w * hreg[i].w;
                s1 += wreg[g][i + 4].x * hreg[i + 4].x + wreg[g][i + 4].y * hreg[i + 4].y
                    + wreg[g][i + 4].z * hreg[i + 4].z + wreg[g][i + 4].w * hreg[i + 4].w;
            }
            float s = s0 + s1;
#pragma unroll
            for (int o = 16; o; o >>= 1) s += __shfl_xor_sync(0xffffffffu, s, o);
            gate[g] = s;                     // every lane holds the sum
        }

        // lanes 0-3 each evaluate one activation
        float a = 0.f;
        if (lane < 4) {
            float pre = xgv + (lane == 0 ? gate[0] : lane == 1 ? gate[1]
                               : lane == 2 ? gate[2] : gate[3]);
            if (lane == 2) {
                a = 1.f - __fdividef(2.f, __expf(2.f * pre) + 1.f);  // tanh
            } else {
                a = __fdividef(1.f, 1.f + __expf(-pre));             // sigmoid
            }
        }
        float i_ = __shfl_sync(0xffffffffu, a, 0);
        float f_ = __shfl_sync(0xffffffffu, a, 1);
        float g_ = __shfl_sync(0xffffffffu, a, 2);
        float o_ = __shfl_sync(0xffffffffu, a, 3);

        float h_ = 0.f;
        if (lane == 0) {
            c_reg = f_ * c_reg + i_ * g_;
            float tc = 1.f - __fdividef(2.f, __expf(2.f * c_reg) + 1.f);
            h_ = o_ * tc;
            g_hbuf[(t + 1) & 1][j] = h_;     // critical-path store
        }
        float h_b = __shfl_sync(0xffffffffu, h_, 0);

        if (t < TT - 1) {
            // prefetch next step's xg; L2 latency hides behind the barrier
            if (lane < 4)
                xgv = __ldcg(&g_xg[(size_t)(t + 1) * G4 + lane * HH + j]);
            __syncthreads();                 // CTA's 8 h-stores done
            if (lane == 1)                   // bookkeeping off tid0's path
                g_hs16[(size_t)t * HH + j] = __float2bfloat16(h_b);
            if (tid == 0) {
                unsigned target = relbase + (unsigned)t + 1u;
                unsigned aold = atom_add_acqrel(&g_arrive, 1u);
                if ((aold + 1u) % (unsigned)NCTA == 0u) {
                    atom_add_release(&g_release, 1u);  // last arriver releases
                } else {
                    while ((int)(ld_acquire(&g_release) - target) < 0) { }
                }
            }
            __syncthreads();
        } else {
            if (lane == 1)
                g_hs16[(size_t)t * HH + j] = __float2bfloat16(h_b);
            if (lane == 0) { out_tail[j] = h_; out_tail[HH + j] = c_reg; }
        }
    }
}

// =================================================================
// Row log-softmax — online max/sum in ONE read pass, then write pass.
// =================================================================
__global__ void __launch_bounds__(256) logsoftmax_kernel(
    const float* __restrict__ scores, float* __restrict__ out)
{
    __shared__ float mred[256];
    __shared__ float sred[256];
    const int row = blockIdx.x;
    const int tid = threadIdx.x;
    const float* s = scores + (size_t)row * VV;

    float m = -3.402823466e38f, su = 0.f;
    for (int v = tid; v < VV; v += 256) {
        float x = s[v];
        if (x > m) { su *= __expf(m - x); m = x; }
        su += __expf(x - m);
    }
    mred[tid] = m; sred[tid] = su; __syncthreads();
    for (int st = 128; st > 0; st >>= 1) {
        if (tid < st) {
            float m2 = mred[tid + st], s2 = sred[tid + st];
            float m1 = mred[tid],      s1 = sred[tid];
            float mn = fmaxf(m1, m2);
            sred[tid] = s1 * __expf(m1 - mn) + s2 * __expf(m2 - mn);
            mred[tid] = mn;
        }
        __syncthreads();
    }
    const float L = mred[0] + logf(sred[0]);

    float* o = out + (size_t)row * VV;
    for (int v = tid; v < VV; v += 256) o[v] = s[v] - L;
}

// =================================================================
extern "C" void kernel_launch(void* const* d_in, const int* in_sizes, int n_in,
                              void* d_out, int out_size)
{
    (void)in_sizes; (void)n_in; (void)out_size;
    const int*   seq   = (const int*)  d_in[0];
    const float* h0    = (const float*)d_in[1];
    const float* c0    = (const float*)d_in[2];
    const float* emb   = (const float*)d_in[3];
    const float* W_ih  = (const float*)d_in[4];
    const float* W_hh  = (const float*)d_in[5];
    const float* b_ih  = (const float*)d_in[6];
    const float* b_hh  = (const float*)d_in[7];
    const float* W_out = (const float*)d_in[8];
    const float* b_out = (const float*)d_in[9];
    float* out = (float*)d_out;

    float *p_xg = nullptr, *p_scores = nullptr;
    __nv_bfloat16 *p_x16 = nullptr, *p_wih16 = nullptr, *p_wout16 = nullptr,
                  *p_hs16 = nullptr;
    cudaGetSymbolAddress((void**)&p_xg, g_xg);
    cudaGetSymbolAddress((void**)&p_scores, g_scores);
    cudaGetSymbolAddress((void**)&p_x16, g_x16);
    cudaGetSymbolAddress((void**)&p_wih16, g_wih16);
    cudaGetSymbolAddress((void**)&p_wout16, g_wout16);
    cudaGetSymbolAddress((void**)&p_hs16, g_hs16);

    // allow 61.4 KB dynamic smem for the pipelined GEMM (host-side
    // attribute set, not captured; same value every call)
    cudaFuncSetAttribute(bgemm_tn, cudaFuncAttributeMaxDynamicSharedMemorySize,
                         BGEMM_SMEM);

    // conversions (vectorized)
    gather_x16_kernel<<<TT, 256>>>(seq, emb);
    f2bf4_kernel<<<512, 256>>>((const float4*)W_ih, (uint2*)p_wih16,
                               (size_t)G4 * EE / 4);
    f2bf4_kernel<<<2048, 256>>>((const float4*)W_out, (uint2*)p_wout16,
                                (size_t)VV * HH / 4);

    // 1) xg = x @ W_ih^T + (b_ih + b_hh)   [T, 4H]
    {
        dim3 grid(G4 / 128, TT / 128);
        bgemm_tn<<<grid, 256, BGEMM_SMEM>>>(p_x16, p_wih16, b_ih, b_hh, p_xg,
                                            TT, G4, EE);
    }
    // 2) sequential LSTM scan
    lstm_scan_kernel<<<NCTA, 256>>>(h0, c0, W_hh, out + (size_t)TT * VV);
    // 3) scores = hs @ W_out^T + b_out     [T, V]
    {
        dim3 grid(VV / 128, TT / 128);
        bgemm_tn<<<grid, 256, BGEMM_SMEM>>>(p_hs16, p_wout16, b_out, nullptr,
                                            p_scores, TT, VV, HH);
    }
    // 4) logp = log_softmax(scores) -> d_out
    logsoftmax_kernel<<<TT, 256>>>(p_scores, out);
}

// round 12
// speedup vs baseline: 1.1238x; 1.1238x over previous
#include <cuda_runtime.h>
#include <cuda_bf16.h>
#include <cstdint>
#include <cstddef>

// Problem constants
#define TT   2048
#define HH   1024
#define EE   1024
#define VV   32000
#define G4   4096
#define NCTA 128
#define UPC  8

// ---------------- scratch (no allocations allowed) ----------------
__device__ float g_xg[(size_t)TT * G4];                       // [T,4H] fp32
__device__ float g_scores[(size_t)TT * VV];                   // [T,V] fp32
__device__ __align__(16) __nv_bfloat16 g_x16[(size_t)TT * EE];
__device__ __align__(16) __nv_bfloat16 g_wih16[(size_t)G4 * EE];
__device__ __align__(16) __nv_bfloat16 g_wout16[(size_t)VV * HH];
__device__ __align__(16) __nv_bfloat16 g_hs16[(size_t)TT * HH];
__device__ float g_hbuf[2][HH];
__device__ unsigned g_arrive;    // monotonic counters (R2/R10-proven, replay-safe)
__device__ unsigned g_release;

// ---------------- conversions ----------------
__global__ void gather_x16_kernel(const int* __restrict__ seq,
                                  const float* __restrict__ emb)
{
    int t = blockIdx.x;
    const float4* src = (const float4*)(emb + (size_t)seq[t] * EE);
    uint2* dst = (uint2*)(g_x16 + (size_t)t * EE);
    int i = threadIdx.x;            // 256 threads, EE/4 = 256 float4
    float4 v = src[i];
    __nv_bfloat162 a = __floats2bfloat162_rn(v.x, v.y);
    __nv_bfloat162 b = __floats2bfloat162_rn(v.z, v.w);
    dst[i] = make_uint2(*(unsigned*)&a, *(unsigned*)&b);
}

__global__ void f2bf4_kernel(const float4* __restrict__ src,
                             uint2* __restrict__ dst, size_t n4)
{
    size_t i = (size_t)blockIdx.x * blockDim.x + threadIdx.x;
    size_t stride = (size_t)gridDim.x * blockDim.x;
    for (; i < n4; i += stride) {
        float4 v = src[i];
        __nv_bfloat162 a = __floats2bfloat162_rn(v.x, v.y);
        __nv_bfloat162 b = __floats2bfloat162_rn(v.z, v.w);
        dst[i] = make_uint2(*(unsigned*)&a, *(unsigned*)&b);
    }
}

// =================================================================
// bf16 tensor-core GEMM — 3-stage cp.async pipeline (R11-measured:
// 71.8us on xg, rel_err identical). Dynamic smem 61,440 B.
// =================================================================
#define SKP 40
#define STG 3
#define STAGE_ELEMS (128 * SKP)

__device__ __forceinline__ void cp16(void* smem, const void* gmem) {
    uint32_t s = (uint32_t)__cvta_generic_to_shared(smem);
    asm volatile("cp.async.cg.shared.global [%0], [%1], 16;" :: "r"(s), "l"(gmem));
}

__device__ __forceinline__ void ldsm_x4(uint32_t& r0, uint32_t& r1,
                                        uint32_t& r2, uint32_t& r3,
                                        const __nv_bfloat16* p)
{
    uint32_t addr = (uint32_t)__cvta_generic_to_shared(p);
    asm volatile("ldmatrix.sync.aligned.m8n8.x4.shared.b16 {%0,%1,%2,%3}, [%4];\n"
                 : "=r"(r0), "=r"(r1), "=r"(r2), "=r"(r3) : "r"(addr));
}

__device__ __forceinline__ void mma16816(float* d, const uint32_t* a,
                                         const uint32_t* b)
{
    asm volatile(
        "mma.sync.aligned.m16n8k16.row.col.f32.bf16.bf16.f32 "
        "{%0,%1,%2,%3}, {%4,%5,%6,%7}, {%8,%9}, {%0,%1,%2,%3};\n"
        : "+f"(d[0]), "+f"(d[1]), "+f"(d[2]), "+f"(d[3])
        : "r"(a[0]), "r"(a[1]), "r"(a[2]), "r"(a[3]), "r"(b[0]), "r"(b[1]));
}

__global__ void __launch_bounds__(256) bgemm_tn(
    const __nv_bfloat16* __restrict__ A, const __nv_bfloat16* __restrict__ B,
    const float* __restrict__ bias1, const float* __restrict__ bias2,
    float* __restrict__ C, int M, int N, int K)
{
    extern __shared__ __nv_bfloat16 smp[];
    __nv_bfloat16* Asm = smp;                     // [STG][STAGE_ELEMS]
    __nv_bfloat16* Bsm = smp + STG * STAGE_ELEMS;

    const int tid = threadIdx.x;
    const int lane = tid & 31;
    const int w = tid >> 5;
    const int wm = w >> 2;
    const int wn = w & 3;
    const int bm = blockIdx.y * 128, bn = blockIdx.x * 128;

    const int c0 = tid, c1 = tid + 256;
    const int r0g = c0 >> 2, k0g = (c0 & 3) * 8;
    const int r1g = c1 >> 2, k1g = (c1 & 3) * 8;
    const __nv_bfloat16* Ap0 = A + (size_t)(bm + r0g) * K + k0g;
    const __nv_bfloat16* Ap1 = A + (size_t)(bm + r1g) * K + k1g;
    const __nv_bfloat16* Bp0 = B + (size_t)(bn + r0g) * K + k0g;
    const __nv_bfloat16* Bp1 = B + (size_t)(bn + r1g) * K + k1g;

    const int so0 = r0g * SKP + k0g;   // smem element offsets (16B aligned)
    const int so1 = r1g * SKP + k1g;

    float acc[4][4][4];
#pragma unroll
    for (int i = 0; i < 4; ++i)
#pragma unroll
        for (int j = 0; j < 4; ++j)
#pragma unroll
            for (int q = 0; q < 4; ++q) acc[i][j][q] = 0.f;

    const int KT = K / 32;

    // prologue: stages 0 and 1 in flight
#pragma unroll
    for (int s = 0; s < STG - 1; ++s) {
        int ko = s * 32;
        __nv_bfloat16* As = Asm + s * STAGE_ELEMS;
        __nv_bfloat16* Bs = Bsm + s * STAGE_ELEMS;
        cp16(As + so0, Ap0 + ko);
        cp16(As + so1, Ap1 + ko);
        cp16(Bs + so0, Bp0 + ko);
        cp16(Bs + so1, Bp1 + ko);
        asm volatile("cp.async.commit_group;" ::: "memory");
    }

    for (int kt = 0; kt < KT; ++kt) {
        asm volatile("cp.async.wait_group %0;" :: "n"(STG - 2) : "memory");
        __syncthreads();

        const int slot = kt % STG;
        const __nv_bfloat16* As = Asm + slot * STAGE_ELEMS;
        const __nv_bfloat16* Bs = Bsm + slot * STAGE_ELEMS;
#pragma unroll
        for (int ks = 0; ks < 2; ++ks) {
            uint32_t af[4][4];
#pragma unroll
            for (int mf = 0; mf < 4; ++mf)
                ldsm_x4(af[mf][0], af[mf][1], af[mf][2], af[mf][3],
                        &As[(wm * 64 + mf * 16 + (lane & 15)) * SKP
                            + ks * 16 + (lane >> 4) * 8]);
            uint32_t bf[4][2];
#pragma unroll
            for (int p = 0; p < 2; ++p) {
                uint32_t r0, r1, r2, r3;
                ldsm_x4(r0, r1, r2, r3,
                        &Bs[(wn * 32 + p * 16 + ((lane >> 4) << 3) + (lane & 7)) * SKP
                            + ks * 16 + ((lane >> 3) & 1) * 8]);
                bf[p * 2][0] = r0; bf[p * 2][1] = r1;
                bf[p * 2 + 1][0] = r2; bf[p * 2 + 1][1] = r3;
            }
#pragma unroll
            for (int mf = 0; mf < 4; ++mf)
#pragma unroll
                for (int nf = 0; nf < 4; ++nf)
                    mma16816(acc[mf][nf], af[mf], bf[nf]);
        }

        // issue stage kt+STG-1 (slot is free: all warps are past the sync)
        int ktn = kt + STG - 1;
        if (ktn < KT) {
            int ko = ktn * 32;
            int ns = ktn % STG;
            __nv_bfloat16* Aw = Asm + ns * STAGE_ELEMS;
            __nv_bfloat16* Bw = Bsm + ns * STAGE_ELEMS;
            cp16(Aw + so0, Ap0 + ko);
            cp16(Aw + so1, Ap1 + ko);
            cp16(Bw + so0, Bp0 + ko);
            cp16(Bw + so1, Bp1 + ko);
        }
        asm volatile("cp.async.commit_group;" ::: "memory"); // lockstep group count
    }

    const int gid = lane >> 2, tg = lane & 3;
#pragma unroll
    for (int mf = 0; mf < 4; ++mf) {
        int row0 = bm + wm * 64 + mf * 16 + gid;
#pragma unroll
        for (int nf = 0; nf < 4; ++nf) {
            int col = bn + wn * 32 + nf * 8 + tg * 2;
            float b0 = 0.f, b1 = 0.f;
            if (bias1) { b0 += bias1[col]; b1 += bias1[col + 1]; }
            if (bias2) { b0 += bias2[col]; b1 += bias2[col + 1]; }
            C[(size_t)row0 * N + col]           = acc[mf][nf][0] + b0;
            C[(size_t)row0 * N + col + 1]       = acc[mf][nf][1] + b1;
            C[(size_t)(row0 + 8) * N + col]     = acc[mf][nf][2] + b0;
            C[(size_t)(row0 + 8) * N + col + 1] = acc[mf][nf][3] + b1;
        }
    }
}
#define BGEMM_SMEM (STG * STAGE_ELEMS * 2 * (int)sizeof(__nv_bfloat16))

// =================================================================
// Persistent LSTM scan — EXACT R10 formulation (5256us, the measured
// optimum over 6 sync variants): threadfence + plain atomicAdd
// arrive/release + volatile poll; monotonic counters + relbase
// (graph-replay safe); parallel activations on lanes 0-3; in-loop xg
// prefetch; hs16 bookkeeping on lane 1.
// =================================================================
__global__ void __launch_bounds__(256, 1) lstm_scan_kernel(
    const float* __restrict__ h0, const float* __restrict__ c0,
    const float* __restrict__ W_hh, float* __restrict__ out_tail)
{
    __shared__ float sh[HH];
    const int tid  = threadIdx.x;
    const int lane = tid & 31;
    const int w    = tid >> 5;
    const int j    = blockIdx.x * UPC + w;

    float4 wreg[4][8];
#pragma unroll
    for (int g = 0; g < 4; ++g)
#pragma unroll
        for (int i = 0; i < 8; ++i)
            wreg[g][i] = *(const float4*)(W_hh + (size_t)(g * HH + j) * HH
                                          + lane * 4 + 128 * i);

    float c_reg = c0[j];
    const unsigned relbase = *(volatile unsigned*)&g_release; // before 1st arrive

    for (int t = 0; t < TT; ++t) {
        const float* hsrc = (t == 0) ? h0 : g_hbuf[t & 1];
        float4 hv = __ldcg((const float4*)hsrc + tid);
        float xgv = 0.f;
        if (lane < 4)
            xgv = __ldcg(&g_xg[(size_t)t * G4 + lane * HH + j]);
        *((float4*)sh + tid) = hv;
        __syncthreads();

        float4 hreg[8];
#pragma unroll
        for (int i = 0; i < 8; ++i)
            hreg[i] = *((const float4*)sh + lane + 32 * i);

        float gate[4];
#pragma unroll
        for (int g = 0; g < 4; ++g) {
            float s0 = 0.f, s1 = 0.f;        // 2 accumulators: halve FFMA chain
#pragma unroll
            for (int i = 0; i < 4; ++i) {
                s0 += wreg[g][i].x * hreg[i].x + wreg[g][i].y * hreg[i].y
                    + wreg[g][i].z * hreg[i].z + wreg[g][i].w * hreg[i].w;
                s1 += wreg[g][i + 4].x * hreg[i + 4].x + wreg[g][i + 4].y * hreg[i + 4].y
                    + wreg[g][i + 4].z * hreg[i + 4].z + wreg[g][i + 4].w * hreg[i + 4].w;
            }
            float s = s0 + s1;
#pragma unroll
            for (int o = 16; o; o >>= 1) s += __shfl_xor_sync(0xffffffffu, s, o);
            gate[g] = s;                     // every lane holds the sum
        }

        // lanes 0-3 each evaluate one activation
        float a = 0.f;
        if (lane < 4) {
            float pre = xgv + (lane == 0 ? gate[0] : lane == 1 ? gate[1]
                               : lane == 2 ? gate[2] : gate[3]);
            if (lane == 2) {
                a = 1.f - __fdividef(2.f, __expf(2.f * pre) + 1.f);  // tanh
            } else {
                a = __fdividef(1.f, 1.f + __expf(-pre));             // sigmoid
            }
        }
        float i_ = __shfl_sync(0xffffffffu, a, 0);
        float f_ = __shfl_sync(0xffffffffu, a, 1);
        float g_ = __shfl_sync(0xffffffffu, a, 2);
        float o_ = __shfl_sync(0xffffffffu, a, 3);

        float h_ = 0.f;
        if (lane == 0) {
            c_reg = f_ * c_reg + i_ * g_;
            float tc = 1.f - __fdividef(2.f, __expf(2.f * c_reg) + 1.f);
            h_ = o_ * tc;
            g_hbuf[(t + 1) & 1][j] = h_;     // critical-path store
        }
        float h_b = __shfl_sync(0xffffffffu, h_, 0);

        if (t < TT - 1) {
            __threadfence();                 // publish h writes (R2/R10-proven)
            __syncthreads();                 // whole CTA done with step t
            if (lane == 1)                   // bookkeeping off tid0's path
                g_hs16[(size_t)t * HH + j] = __float2bfloat16(h_b);
            if (tid == 0) {
                unsigned target = relbase + (unsigned)t + 1u;
                unsigned aold = atomicAdd(&g_arrive, 1u);
                if ((aold + 1u) % (unsigned)NCTA == 0u) {
                    atomicAdd(&g_release, 1u);   // last arriver releases all
                } else {
                    while ((int)(*(volatile unsigned*)&g_release - target) < 0) { }
                }
            }
            __syncthreads();
        } else {
            if (lane == 1)
                g_hs16[(size_t)t * HH + j] = __float2bfloat16(h_b);
            if (lane == 0) { out_tail[j] = h_; out_tail[HH + j] = c_reg; }
        }
    }
}

// =================================================================
// Row log-softmax — online max/sum in ONE read pass, then write pass.
// =================================================================
__global__ void __launch_bounds__(256) logsoftmax_kernel(
    const float* __restrict__ scores, float* __restrict__ out)
{
    __shared__ float mred[256];
    __shared__ float sred[256];
    const int row = blockIdx.x;
    const int tid = threadIdx.x;
    const float* s = scores + (size_t)row * VV;

    float m = -3.402823466e38f, su = 0.f;
    for (int v = tid; v < VV; v += 256) {
        float x = s[v];
        if (x > m) { su *= __expf(m - x); m = x; }
        su += __expf(x - m);
    }
    mred[tid] = m; sred[tid] = su; __syncthreads();
    for (int st = 128; st > 0; st >>= 1) {
        if (tid < st) {
            float m2 = mred[tid + st], s2 = sred[tid + st];
            float m1 = mred[tid],      s1 = sred[tid];
            float mn = fmaxf(m1, m2);
            sred[tid] = s1 * __expf(m1 - mn) + s2 * __expf(m2 - mn);
            mred[tid] = mn;
        }
        __syncthreads();
    }
    const float L = mred[0] + logf(sred[0]);

    float* o = out + (size_t)row * VV;
    for (int v = tid; v < VV; v += 256) o[v] = s[v] - L;
}

// =================================================================
extern "C" void kernel_launch(void* const* d_in, const int* in_sizes, int n_in,
                              void* d_out, int out_size)
{
    (void)in_sizes; (void)n_in; (void)out_size;
    const int*   seq   = (const int*)  d_in[0];
    const float* h0    = (const float*)d_in[1];
    const float* c0    = (const float*)d_in[2];
    const float* emb   = (const float*)d_in[3];
    const float* W_ih  = (const float*)d_in[4];
    const float* W_hh  = (const float*)d_in[5];
    const float* b_ih  = (const float*)d_in[6];
    const float* b_hh  = (const float*)d_in[7];
    const float* W_out = (const float*)d_in[8];
    const float* b_out = (const float*)d_in[9];
    float* out = (float*)d_out;

    float *p_xg = nullptr, *p_scores = nullptr;
    __nv_bfloat16 *p_x16 = nullptr, *p_wih16 = nullptr, *p_wout16 = nullptr,
                  *p_hs16 = nullptr;
    cudaGetSymbolAddress((void**)&p_xg, g_xg);
    cudaGetSymbolAddress((void**)&p_scores, g_scores);
    cudaGetSymbolAddress((void**)&p_x16, g_x16);
    cudaGetSymbolAddress((void**)&p_wih16, g_wih16);
    cudaGetSymbolAddress((void**)&p_wout16, g_wout16);
    cudaGetSymbolAddress((void**)&p_hs16, g_hs16);

    // allow 61.4 KB dynamic smem for the pipelined GEMM
    cudaFuncSetAttribute(bgemm_tn, cudaFuncAttributeMaxDynamicSharedMemorySize,
                         BGEMM_SMEM);

    // conversions (vectorized)
    gather_x16_kernel<<<TT, 256>>>(seq, emb);
    f2bf4_kernel<<<512, 256>>>((const float4*)W_ih, (uint2*)p_wih16,
                               (size_t)G4 * EE / 4);
    f2bf4_kernel<<<2048, 256>>>((const float4*)W_out, (uint2*)p_wout16,
                                (size_t)VV * HH / 4);

    // 1) xg = x @ W_ih^T + (b_ih + b_hh)   [T, 4H]
    {
        dim3 grid(G4 / 128, TT / 128);
        bgemm_tn<<<grid, 256, BGEMM_SMEM>>>(p_x16, p_wih16, b_ih, b_hh, p_xg,
                                            TT, G4, EE);
    }
    // 2) sequential LSTM scan
    lstm_scan_kernel<<<NCTA, 256>>>(h0, c0, W_hh, out + (size_t)TT * VV);
    // 3) scores = hs @ W_out^T + b_out     [T, V]
    {
        dim3 grid(VV / 128, TT / 128);
        bgemm_tn<<<grid, 256, BGEMM_SMEM>>>(p_hs16, p_wout16, b_out, nullptr,
                                            p_scores, TT, VV, HH);
    }
    // 4) logp = log_softmax(scores) -> d_out
    logsoftmax_kernel<<<TT, 256>>>(p_scores, out);
}

// round 13
// speedup vs baseline: 1.1602x; 1.0324x over previous
#include <cuda_runtime.h>
#include <cuda_bf16.h>
#include <cstdint>
#include <cstddef>

// Problem constants
#define TT   2048
#define HH   1024
#define EE   1024
#define VV   32000
#define G4   4096
#define NCTA 128
#define UPC  8

// ---------------- scratch (no allocations allowed) ----------------
__device__ float g_xg[(size_t)TT * G4];                       // [T,4H] fp32
__device__ float g_scores[(size_t)TT * VV];                   // [T,V] fp32
__device__ __align__(16) __nv_bfloat16 g_x16[(size_t)TT * EE];
__device__ __align__(16) __nv_bfloat16 g_wih16[(size_t)G4 * EE];
__device__ __align__(16) __nv_bfloat16 g_wout16[(size_t)VV * HH];
__device__ __align__(16) __nv_bfloat16 g_hs16[(size_t)TT * HH];
__device__ float g_hbuf[2][HH];
__device__ unsigned g_arrive;    // monotonic counters (R2/R10-proven, replay-safe)
__device__ unsigned g_release;

// packed f32x2 fused multiply-add (Blackwell FFMA2; PTX-only path)
__device__ __forceinline__ unsigned long long fma2(
    unsigned long long a, unsigned long long b, unsigned long long c)
{
    unsigned long long d;
    asm("fma.rn.f32x2 %0, %1, %2, %3;" : "=l"(d) : "l"(a), "l"(b), "l"(c));
    return d;
}

// ---------------- conversions ----------------
__global__ void gather_x16_kernel(const int* __restrict__ seq,
                                  const float* __restrict__ emb)
{
    int t = blockIdx.x;
    const float4* src = (const float4*)(emb + (size_t)seq[t] * EE);
    uint2* dst = (uint2*)(g_x16 + (size_t)t * EE);
    int i = threadIdx.x;            // 256 threads, EE/4 = 256 float4
    float4 v = src[i];
    __nv_bfloat162 a = __floats2bfloat162_rn(v.x, v.y);
    __nv_bfloat162 b = __floats2bfloat162_rn(v.z, v.w);
    dst[i] = make_uint2(*(unsigned*)&a, *(unsigned*)&b);
}

__global__ void f2bf4_kernel(const float4* __restrict__ src,
                             uint2* __restrict__ dst, size_t n4)
{
    size_t i = (size_t)blockIdx.x * blockDim.x + threadIdx.x;
    size_t stride = (size_t)gridDim.x * blockDim.x;
    for (; i < n4; i += stride) {
        float4 v = src[i];
        __nv_bfloat162 a = __floats2bfloat162_rn(v.x, v.y);
        __nv_bfloat162 b = __floats2bfloat162_rn(v.z, v.w);
        dst[i] = make_uint2(*(unsigned*)&a, *(unsigned*)&b);
    }
}

// =================================================================
// bf16 tensor-core GEMM — 3-stage cp.async pipeline (R11/R12-proven)
// =================================================================
#define SKP 40
#define STG 3
#define STAGE_ELEMS (128 * SKP)

__device__ __forceinline__ void cp16(void* smem, const void* gmem) {
    uint32_t s = (uint32_t)__cvta_generic_to_shared(smem);
    asm volatile("cp.async.cg.shared.global [%0], [%1], 16;" :: "r"(s), "l"(gmem));
}

__device__ __forceinline__ void ldsm_x4(uint32_t& r0, uint32_t& r1,
                                        uint32_t& r2, uint32_t& r3,
                                        const __nv_bfloat16* p)
{
    uint32_t addr = (uint32_t)__cvta_generic_to_shared(p);
    asm volatile("ldmatrix.sync.aligned.m8n8.x4.shared.b16 {%0,%1,%2,%3}, [%4];\n"
                 : "=r"(r0), "=r"(r1), "=r"(r2), "=r"(r3) : "r"(addr));
}

__device__ __forceinline__ void mma16816(float* d, const uint32_t* a,
                                         const uint32_t* b)
{
    asm volatile(
        "mma.sync.aligned.m16n8k16.row.col.f32.bf16.bf16.f32 "
        "{%0,%1,%2,%3}, {%4,%5,%6,%7}, {%8,%9}, {%0,%1,%2,%3};\n"
        : "+f"(d[0]), "+f"(d[1]), "+f"(d[2]), "+f"(d[3])
        : "r"(a[0]), "r"(a[1]), "r"(a[2]), "r"(a[3]), "r"(b[0]), "r"(b[1]));
}

__global__ void __launch_bounds__(256) bgemm_tn(
    const __nv_bfloat16* __restrict__ A, const __nv_bfloat16* __restrict__ B,
    const float* __restrict__ bias1, const float* __restrict__ bias2,
    float* __restrict__ C, int M, int N, int K)
{
    extern __shared__ __nv_bfloat16 smp[];
    __nv_bfloat16* Asm = smp;                     // [STG][STAGE_ELEMS]
    __nv_bfloat16* Bsm = smp + STG * STAGE_ELEMS;

    const int tid = threadIdx.x;
    const int lane = tid & 31;
    const int w = tid >> 5;
    const int wm = w >> 2;
    const int wn = w & 3;
    const int bm = blockIdx.y * 128, bn = blockIdx.x * 128;

    const int c0 = tid, c1 = tid + 256;
    const int r0g = c0 >> 2, k0g = (c0 & 3) * 8;
    const int r1g = c1 >> 2, k1g = (c1 & 3) * 8;
    const __nv_bfloat16* Ap0 = A + (size_t)(bm + r0g) * K + k0g;
    const __nv_bfloat16* Ap1 = A + (size_t)(bm + r1g) * K + k1g;
    const __nv_bfloat16* Bp0 = B + (size_t)(bn + r0g) * K + k0g;
    const __nv_bfloat16* Bp1 = B + (size_t)(bn + r1g) * K + k1g;

    const int so0 = r0g * SKP + k0g;   // smem element offsets (16B aligned)
    const int so1 = r1g * SKP + k1g;

    float acc[4][4][4];
#pragma unroll
    for (int i = 0; i < 4; ++i)
#pragma unroll
        for (int j = 0; j < 4; ++j)
#pragma unroll
            for (int q = 0; q < 4; ++q) acc[i][j][q] = 0.f;

    const int KT = K / 32;

    // prologue: stages 0 and 1 in flight
#pragma unroll
    for (int s = 0; s < STG - 1; ++s) {
        int ko = s * 32;
        __nv_bfloat16* As = Asm + s * STAGE_ELEMS;
        __nv_bfloat16* Bs = Bsm + s * STAGE_ELEMS;
        cp16(As + so0, Ap0 + ko);
        cp16(As + so1, Ap1 + ko);
        cp16(Bs + so0, Bp0 + ko);
        cp16(Bs + so1, Bp1 + ko);
        asm volatile("cp.async.commit_group;" ::: "memory");
    }

    for (int kt = 0; kt < KT; ++kt) {
        asm volatile("cp.async.wait_group %0;" :: "n"(STG - 2) : "memory");
        __syncthreads();

        const int slot = kt % STG;
        const __nv_bfloat16* As = Asm + slot * STAGE_ELEMS;
        const __nv_bfloat16* Bs = Bsm + slot * STAGE_ELEMS;
#pragma unroll
        for (int ks = 0; ks < 2; ++ks) {
            uint32_t af[4][4];
#pragma unroll
            for (int mf = 0; mf < 4; ++mf)
                ldsm_x4(af[mf][0], af[mf][1], af[mf][2], af[mf][3],
                        &As[(wm * 64 + mf * 16 + (lane & 15)) * SKP
                            + ks * 16 + (lane >> 4) * 8]);
            uint32_t bf[4][2];
#pragma unroll
            for (int p = 0; p < 2; ++p) {
                uint32_t r0, r1, r2, r3;
                ldsm_x4(r0, r1, r2, r3,
                        &Bs[(wn * 32 + p * 16 + ((lane >> 4) << 3) + (lane & 7)) * SKP
                            + ks * 16 + ((lane >> 3) & 1) * 8]);
                bf[p * 2][0] = r0; bf[p * 2][1] = r1;
                bf[p * 2 + 1][0] = r2; bf[p * 2 + 1][1] = r3;
            }
#pragma unroll
            for (int mf = 0; mf < 4; ++mf)
#pragma unroll
                for (int nf = 0; nf < 4; ++nf)
                    mma16816(acc[mf][nf], af[mf], bf[nf]);
        }

        // issue stage kt+STG-1 (slot is free: all warps are past the sync)
        int ktn = kt + STG - 1;
        if (ktn < KT) {
            int ko = ktn * 32;
            int ns = ktn % STG;
            __nv_bfloat16* Aw = Asm + ns * STAGE_ELEMS;
            __nv_bfloat16* Bw = Bsm + ns * STAGE_ELEMS;
            cp16(Aw + so0, Ap0 + ko);
            cp16(Aw + so1, Ap1 + ko);
            cp16(Bw + so0, Bp0 + ko);
            cp16(Bw + so1, Bp1 + ko);
        }
        asm volatile("cp.async.commit_group;" ::: "memory"); // lockstep group count
    }

    const int gid = lane >> 2, tg = lane & 3;
#pragma unroll
    for (int mf = 0; mf < 4; ++mf) {
        int row0 = bm + wm * 64 + mf * 16 + gid;
#pragma unroll
        for (int nf = 0; nf < 4; ++nf) {
            int col = bn + wn * 32 + nf * 8 + tg * 2;
            float b0 = 0.f, b1 = 0.f;
            if (bias1) { b0 += bias1[col]; b1 += bias1[col + 1]; }
            if (bias2) { b0 += bias2[col]; b1 += bias2[col + 1]; }
            C[(size_t)row0 * N + col]           = acc[mf][nf][0] + b0;
            C[(size_t)row0 * N + col + 1]       = acc[mf][nf][1] + b1;
            C[(size_t)(row0 + 8) * N + col]     = acc[mf][nf][2] + b0;
            C[(size_t)(row0 + 8) * N + col + 1] = acc[mf][nf][3] + b1;
        }
    }
}
#define BGEMM_SMEM (STG * STAGE_ELEMS * 2 * (int)sizeof(__nv_bfloat16))

// =================================================================
// Persistent LSTM scan — R10 barrier (measured optimum over 6
// variants), dot products on packed FFMA2 (fma.rn.f32x2): 64 packed
// FMA/lane instead of 128 scalar -> halves the fp32 issue floor.
// Weights/h held as ulonglong2 register arrays (loaded packed, never
// address-cast -> no local-mem spill).
// =================================================================
__global__ void __launch_bounds__(256, 1) lstm_scan_kernel(
    const float* __restrict__ h0, const float* __restrict__ c0,
    const float* __restrict__ W_hh, float* __restrict__ out_tail)
{
    __shared__ float sh[HH];
    const int tid  = threadIdx.x;
    const int lane = tid & 31;
    const int w    = tid >> 5;
    const int j    = blockIdx.x * UPC + w;

    // W_hh rows as packed f32x2 pairs: wreg[g][i] = 4 floats (2 pairs)
    ulonglong2 wreg[4][8];
#pragma unroll
    for (int g = 0; g < 4; ++g)
#pragma unroll
        for (int i = 0; i < 8; ++i)
            wreg[g][i] = *(const ulonglong2*)(W_hh + (size_t)(g * HH + j) * HH
                                              + lane * 4 + 128 * i);

    float c_reg = c0[j];
    const unsigned relbase = *(volatile unsigned*)&g_release; // before 1st arrive

    for (int t = 0; t < TT; ++t) {
        const float* hsrc = (t == 0) ? h0 : g_hbuf[t & 1];
        float4 hv = __ldcg((const float4*)hsrc + tid);
        float xgv = 0.f;
        if (lane < 4)
            xgv = __ldcg(&g_xg[(size_t)t * G4 + lane * HH + j]);
        *((float4*)sh + tid) = hv;
        __syncthreads();

        ulonglong2 hreg[8];
#pragma unroll
        for (int i = 0; i < 8; ++i)
            hreg[i] = *((const ulonglong2*)sh + lane + 32 * i);

        float gate[4];
#pragma unroll
        for (int g = 0; g < 4; ++g) {
            unsigned long long a0 = 0ull, a1 = 0ull;   // 2x f32x2 accumulators
#pragma unroll
            for (int i = 0; i < 8; ++i) {
                a0 = fma2(wreg[g][i].x, hreg[i].x, a0);
                a1 = fma2(wreg[g][i].y, hreg[i].y, a1);
            }
            float lo0, hi0, lo1, hi1;
            asm("mov.b64 {%0,%1}, %2;" : "=f"(lo0), "=f"(hi0) : "l"(a0));
            asm("mov.b64 {%0,%1}, %2;" : "=f"(lo1), "=f"(hi1) : "l"(a1));
            float s = (lo0 + hi0) + (lo1 + hi1);
#pragma unroll
            for (int o = 16; o; o >>= 1) s += __shfl_xor_sync(0xffffffffu, s, o);
            gate[g] = s;                     // every lane holds the sum
        }

        // lanes 0-3 each evaluate one activation
        float a = 0.f;
        if (lane < 4) {
            float pre = xgv + (lane == 0 ? gate[0] : lane == 1 ? gate[1]
                               : lane == 2 ? gate[2] : gate[3]);
            if (lane == 2) {
                a = 1.f - __fdividef(2.f, __expf(2.f * pre) + 1.f);  // tanh
            } else {
                a = __fdividef(1.f, 1.f + __expf(-pre));             // sigmoid
            }
        }
        float i_ = __shfl_sync(0xffffffffu, a, 0);
        float f_ = __shfl_sync(0xffffffffu, a, 1);
        float g_ = __shfl_sync(0xffffffffu, a, 2);
        float o_ = __shfl_sync(0xffffffffu, a, 3);

        float h_ = 0.f;
        if (lane == 0) {
            c_reg = f_ * c_reg + i_ * g_;
            float tc = 1.f - __fdividef(2.f, __expf(2.f * c_reg) + 1.f);
            h_ = o_ * tc;
            g_hbuf[(t + 1) & 1][j] = h_;     // critical-path store
        }
        float h_b = __shfl_sync(0xffffffffu, h_, 0);

        if (t < TT - 1) {
            __threadfence();                 // publish h writes (R2/R10-proven)
            __syncthreads();                 // whole CTA done with step t
            if (lane == 1)                   // bookkeeping off tid0's path
                g_hs16[(size_t)t * HH + j] = __float2bfloat16(h_b);
            if (tid == 0) {
                unsigned target = relbase + (unsigned)t + 1u;
                unsigned aold = atomicAdd(&g_arrive, 1u);
                if ((aold + 1u) % (unsigned)NCTA == 0u) {
                    atomicAdd(&g_release, 1u);   // last arriver releases all
                } else {
                    while ((int)(*(volatile unsigned*)&g_release - target) < 0) { }
                }
            }
            __syncthreads();
        } else {
            if (lane == 1)
                g_hs16[(size_t)t * HH + j] = __float2bfloat16(h_b);
            if (lane == 0) { out_tail[j] = h_; out_tail[HH + j] = c_reg; }
        }
    }
}

// =================================================================
// Row log-softmax — online max/sum in ONE read pass, then write pass.
// =================================================================
__global__ void __launch_bounds__(256) logsoftmax_kernel(
    const float* __restrict__ scores, float* __restrict__ out)
{
    __shared__ float mred[256];
    __shared__ float sred[256];
    const int row = blockIdx.x;
    const int tid = threadIdx.x;
    const float* s = scores + (size_t)row * VV;

    float m = -3.402823466e38f, su = 0.f;
    for (int v = tid; v < VV; v += 256) {
        float x = s[v];
        if (x > m) { su *= __expf(m - x); m = x; }
        su += __expf(x - m);
    }
    mred[tid] = m; sred[tid] = su; __syncthreads();
    for (int st = 128; st > 0; st >>= 1) {
        if (tid < st) {
            float m2 = mred[tid + st], s2 = sred[tid + st];
            float m1 = mred[tid],      s1 = sred[tid];
            float mn = fmaxf(m1, m2);
            sred[tid] = s1 * __expf(m1 - mn) + s2 * __expf(m2 - mn);
            mred[tid] = mn;
        }
        __syncthreads();
    }
    const float L = mred[0] + logf(sred[0]);

    float* o = out + (size_t)row * VV;
    for (int v = tid; v < VV; v += 256) o[v] = s[v] - L;
}

// =================================================================
extern "C" void kernel_launch(void* const* d_in, const int* in_sizes, int n_in,
                              void* d_out, int out_size)
{
    (void)in_sizes; (void)n_in; (void)out_size;
    const int*   seq   = (const int*)  d_in[0];
    const float* h0    = (const float*)d_in[1];
    const float* c0    = (const float*)d_in[2];
    const float* emb   = (const float*)d_in[3];
    const float* W_ih  = (const float*)d_in[4];
    const float* W_hh  = (const float*)d_in[5];
    const float* b_ih  = (const float*)d_in[6];
    const float* b_hh  = (const float*)d_in[7];
    const float* W_out = (const float*)d_in[8];
    const float* b_out = (const float*)d_in[9];
    float* out = (float*)d_out;

    float *p_xg = nullptr, *p_scores = nullptr;
    __nv_bfloat16 *p_x16 = nullptr, *p_wih16 = nullptr, *p_wout16 = nullptr,
                  *p_hs16 = nullptr;
    cudaGetSymbolAddress((void**)&p_xg, g_xg);
    cudaGetSymbolAddress((void**)&p_scores, g_scores);
    cudaGetSymbolAddress((void**)&p_x16, g_x16);
    cudaGetSymbolAddress((void**)&p_wih16, g_wih16);
    cudaGetSymbolAddress((void**)&p_wout16, g_wout16);
    cudaGetSymbolAddress((void**)&p_hs16, g_hs16);

    // allow 61.4 KB dynamic smem for the pipelined GEMM
    cudaFuncSetAttribute(bgemm_tn, cudaFuncAttributeMaxDynamicSharedMemorySize,
                         BGEMM_SMEM);

    // conversions (vectorized)
    gather_x16_kernel<<<TT, 256>>>(seq, emb);
    f2bf4_kernel<<<512, 256>>>((const float4*)W_ih, (uint2*)p_wih16,
                               (size_t)G4 * EE / 4);
    f2bf4_kernel<<<2048, 256>>>((const float4*)W_out, (uint2*)p_wout16,
                                (size_t)VV * HH / 4);

    // 1) xg = x @ W_ih^T + (b_ih + b_hh)   [T, 4H]
    {
        dim3 grid(G4 / 128, TT / 128);
        bgemm_tn<<<grid, 256, BGEMM_SMEM>>>(p_x16, p_wih16, b_ih, b_hh, p_xg,
                                            TT, G4, EE);
    }
    // 2) sequential LSTM scan
    lstm_scan_kernel<<<NCTA, 256>>>(h0, c0, W_hh, out + (size_t)TT * VV);
    // 3) scores = hs @ W_out^T + b_out     [T, V]
    {
        dim3 grid(VV / 128, TT / 128);
        bgemm_tn<<<grid, 256, BGEMM_SMEM>>>(p_hs16, p_wout16, b_out, nullptr,
                                            p_scores, TT, VV, HH);
    }
    // 4) logp = log_softmax(scores) -> d_out
    logsoftmax_kernel<<<TT, 256>>>(p_scores, out);
}

// round 16
// speedup vs baseline: 1.1608x; 1.0005x over previous
#include <cuda_runtime.h>
#include <cuda_bf16.h>
#include <cstdint>
#include <cstddef>

// Problem constants
#define TT   2048
#define HH   1024
#define EE   1024
#define VV   32000
#define G4   4096
#define NCTA 128
#define UPC  8

// ---------------- scratch (no allocations allowed) ----------------
__device__ float g_xg[(size_t)TT * G4];                       // [T,4H] fp32
__device__ float g_scores[(size_t)TT * VV];                   // [T,V] fp32
__device__ __align__(16) __nv_bfloat16 g_x16[(size_t)TT * EE];
__device__ __align__(16) __nv_bfloat16 g_wih16[(size_t)G4 * EE];
__device__ __align__(16) __nv_bfloat16 g_wout16[(size_t)VV * HH];
__device__ __align__(16) __nv_bfloat16 g_hs16[(size_t)TT * HH];
__device__ float g_hbuf[2][HH];
__device__ unsigned g_arrive;    // monotonic counters (R2/R10-proven, replay-safe)
__device__ unsigned g_release;

// packed f32x2 fused multiply-add (Blackwell FFMA2; PTX-only path)
__device__ __forceinline__ unsigned long long fma2(
    unsigned long long a, unsigned long long b, unsigned long long c)
{
    unsigned long long d;
    asm("fma.rn.f32x2 %0, %1, %2, %3;" : "=l"(d) : "l"(a), "l"(b), "l"(c));
    return d;
}

// ---------------- conversions ----------------
__global__ void gather_x16_kernel(const int* __restrict__ seq,
                                  const float* __restrict__ emb)
{
    int t = blockIdx.x;
    const float4* src = (const float4*)(emb + (size_t)seq[t] * EE);
    uint2* dst = (uint2*)(g_x16 + (size_t)t * EE);
    int i = threadIdx.x;            // 256 threads, EE/4 = 256 float4
    float4 v = src[i];
    __nv_bfloat162 a = __floats2bfloat162_rn(v.x, v.y);
    __nv_bfloat162 b = __floats2bfloat162_rn(v.z, v.w);
    dst[i] = make_uint2(*(unsigned*)&a, *(unsigned*)&b);
}

__global__ void f2bf4_kernel(const float4* __restrict__ src,
                             uint2* __restrict__ dst, size_t n4)
{
    size_t i = (size_t)blockIdx.x * blockDim.x + threadIdx.x;
    size_t stride = (size_t)gridDim.x * blockDim.x;
    for (; i < n4; i += stride) {
        float4 v = src[i];
        __nv_bfloat162 a = __floats2bfloat162_rn(v.x, v.y);
        __nv_bfloat162 b = __floats2bfloat162_rn(v.z, v.w);
        dst[i] = make_uint2(*(unsigned*)&a, *(unsigned*)&b);
    }
}

// =================================================================
// bf16 tensor-core GEMM — 3-stage cp.async pipeline.
// __launch_bounds__(256, 2): 128 regs x 256 thr x 2 CTAs = exactly
// the 64K-reg RF; smem 2 x 61.4KB = 122.9KB of 228KB. Two resident
// CTAs interleave mma into each other's sync/load bubbles.
// =================================================================
#define SKP 40
#define STG 3
#define STAGE_ELEMS (128 * SKP)

__device__ __forceinline__ void cp16(void* smem, const void* gmem) {
    uint32_t s = (uint32_t)__cvta_generic_to_shared(smem);
    asm volatile("cp.async.cg.shared.global [%0], [%1], 16;" :: "r"(s), "l"(gmem));
}

__device__ __forceinline__ void ldsm_x4(uint32_t& r0, uint32_t& r1,
                                        uint32_t& r2, uint32_t& r3,
                                        const __nv_bfloat16* p)
{
    uint32_t addr = (uint32_t)__cvta_generic_to_shared(p);
    asm volatile("ldmatrix.sync.aligned.m8n8.x4.shared.b16 {%0,%1,%2,%3}, [%4];\n"
                 : "=r"(r0), "=r"(r1), "=r"(r2), "=r"(r3) : "r"(addr));
}

__device__ __forceinline__ void mma16816(float* d, const uint32_t* a,
                                         const uint32_t* b)
{
    asm volatile(
        "mma.sync.aligned.m16n8k16.row.col.f32.bf16.bf16.f32 "
        "{%0,%1,%2,%3}, {%4,%5,%6,%7}, {%8,%9}, {%0,%1,%2,%3};\n"
        : "+f"(d[0]), "+f"(d[1]), "+f"(d[2]), "+f"(d[3])
        : "r"(a[0]), "r"(a[1]), "r"(a[2]), "r"(a[3]), "r"(b[0]), "r"(b[1]));
}

__global__ void __launch_bounds__(256, 2) bgemm_tn(
    const __nv_bfloat16* __restrict__ A, const __nv_bfloat16* __restrict__ B,
    const float* __restrict__ bias1, const float* __restrict__ bias2,
    float* __restrict__ C, int M, int N, int K)
{
    extern __shared__ __nv_bfloat16 smp[];
    __nv_bfloat16* Asm = smp;                     // [STG][STAGE_ELEMS]
    __nv_bfloat16* Bsm = smp + STG * STAGE_ELEMS;

    const int tid = threadIdx.x;
    const int lane = tid & 31;
    const int w = tid >> 5;
    const int wm = w >> 2;
    const int wn = w & 3;
    const int bm = blockIdx.y * 128, bn = blockIdx.x * 128;

    const int c0 = tid, c1 = tid + 256;
    const int r0g = c0 >> 2, k0g = (c0 & 3) * 8;
    const int r1g = c1 >> 2, k1g = (c1 & 3) * 8;
    const __nv_bfloat16* Ap0 = A + (size_t)(bm + r0g) * K + k0g;
    const __nv_bfloat16* Ap1 = A + (size_t)(bm + r1g) * K + k1g;
    const __nv_bfloat16* Bp0 = B + (size_t)(bn + r0g) * K + k0g;
    const __nv_bfloat16* Bp1 = B + (size_t)(bn + r1g) * K + k1g;

    const int so0 = r0g * SKP + k0g;   // smem element offsets (16B aligned)
    const int so1 = r1g * SKP + k1g;

    float acc[4][4][4];
#pragma unroll
    for (int i = 0; i < 4; ++i)
#pragma unroll
        for (int j = 0; j < 4; ++j)
#pragma unroll
            for (int q = 0; q < 4; ++q) acc[i][j][q] = 0.f;

    const int KT = K / 32;

    // prologue: stages 0 and 1 in flight
#pragma unroll
    for (int s = 0; s < STG - 1; ++s) {
        int ko = s * 32;
        __nv_bfloat16* As = Asm + s * STAGE_ELEMS;
        __nv_bfloat16* Bs = Bsm + s * STAGE_ELEMS;
        cp16(As + so0, Ap0 + ko);
        cp16(As + so1, Ap1 + ko);
        cp16(Bs + so0, Bp0 + ko);
        cp16(Bs + so1, Bp1 + ko);
        asm volatile("cp.async.commit_group;" ::: "memory");
    }

    for (int kt = 0; kt < KT; ++kt) {
        asm volatile("cp.async.wait_group %0;" :: "n"(STG - 2) : "memory");
        __syncthreads();

        const int slot = kt % STG;
        const __nv_bfloat16* As = Asm + slot * STAGE_ELEMS;
        const __nv_bfloat16* Bs = Bsm + slot * STAGE_ELEMS;
#pragma unroll
        for (int ks = 0; ks < 2; ++ks) {
            uint32_t af[4][4];
#pragma unroll
            for (int mf = 0; mf < 4; ++mf)
                ldsm_x4(af[mf][0], af[mf][1], af[mf][2], af[mf][3],
                        &As[(wm * 64 + mf * 16 + (lane & 15)) * SKP
                            + ks * 16 + (lane >> 4) * 8]);
            uint32_t bf[4][2];
#pragma unroll
            for (int p = 0; p < 2; ++p) {
                uint32_t r0, r1, r2, r3;
                ldsm_x4(r0, r1, r2, r3,
                        &Bs[(wn * 32 + p * 16 + ((lane >> 4) << 3) + (lane & 7)) * SKP
                            + ks * 16 + ((lane >> 3) & 1) * 8]);
                bf[p * 2][0] = r0; bf[p * 2][1] = r1;
                bf[p * 2 + 1][0] = r2; bf[p * 2 + 1][1] = r3;
            }
#pragma unroll
            for (int mf = 0; mf < 4; ++mf)
#pragma unroll
                for (int nf = 0; nf < 4; ++nf)
                    mma16816(acc[mf][nf], af[mf], bf[nf]);
        }

        // issue stage kt+STG-1 (slot is free: all warps are past the sync)
        int ktn = kt + STG - 1;
        if (ktn < KT) {
            int ko = ktn * 32;
            int ns = ktn % STG;
            __nv_bfloat16* Aw = Asm + ns * STAGE_ELEMS;
            __nv_bfloat16* Bw = Bsm + ns * STAGE_ELEMS;
            cp16(Aw + so0, Ap0 + ko);
            cp16(Aw + so1, Ap1 + ko);
            cp16(Bw + so0, Bp0 + ko);
            cp16(Bw + so1, Bp1 + ko);
        }
        asm volatile("cp.async.commit_group;" ::: "memory"); // lockstep group count
    }

    const int gid = lane >> 2, tg = lane & 3;
#pragma unroll
    for (int mf = 0; mf < 4; ++mf) {
        int row0 = bm + wm * 64 + mf * 16 + gid;
#pragma unroll
        for (int nf = 0; nf < 4; ++nf) {
            int col = bn + wn * 32 + nf * 8 + tg * 2;
            float b0 = 0.f, b1 = 0.f;
            if (bias1) { b0 += bias1[col]; b1 += bias1[col + 1]; }
            if (bias2) { b0 += bias2[col]; b1 += bias2[col + 1]; }
            C[(size_t)row0 * N + col]           = acc[mf][nf][0] + b0;
            C[(size_t)row0 * N + col + 1]       = acc[mf][nf][1] + b1;
            C[(size_t)(row0 + 8) * N + col]     = acc[mf][nf][2] + b0;
            C[(size_t)(row0 + 8) * N + col + 1] = acc[mf][nf][3] + b1;
        }
    }
}
#define BGEMM_SMEM (STG * STAGE_ELEMS * 2 * (int)sizeof(__nv_bfloat16))

// =================================================================
// Persistent LSTM scan — R10 barrier (measured optimum over 6
// variants) + FFMA2 dot products (R13-proven). Untouched this round.
// =================================================================
__global__ void __launch_bounds__(256, 1) lstm_scan_kernel(
    const float* __restrict__ h0, const float* __restrict__ c0,
    const float* __restrict__ W_hh, float* __restrict__ out_tail)
{
    __shared__ float sh[HH];
    const int tid  = threadIdx.x;
    const int lane = tid & 31;
    const int w    = tid >> 5;
    const int j    = blockIdx.x * UPC + w;

    // W_hh rows as packed f32x2 pairs: wreg[g][i] = 4 floats (2 pairs)
    ulonglong2 wreg[4][8];
#pragma unroll
    for (int g = 0; g < 4; ++g)
#pragma unroll
        for (int i = 0; i < 8; ++i)
            wreg[g][i] = *(const ulonglong2*)(W_hh + (size_t)(g * HH + j) * HH
                                              + lane * 4 + 128 * i);

    float c_reg = c0[j];
    const unsigned relbase = *(volatile unsigned*)&g_release; // before 1st arrive

    for (int t = 0; t < TT; ++t) {
        const float* hsrc = (t == 0) ? h0 : g_hbuf[t & 1];
        float4 hv = __ldcg((const float4*)hsrc + tid);
        float xgv = 0.f;
        if (lane < 4)
            xgv = __ldcg(&g_xg[(size_t)t * G4 + lane * HH + j]);
        *((float4*)sh + tid) = hv;
        __syncthreads();

        ulonglong2 hreg[8];
#pragma unroll
        for (int i = 0; i < 8; ++i)
            hreg[i] = *((const ulonglong2*)sh + lane + 32 * i);

        float gate[4];
#pragma unroll
        for (int g = 0; g < 4; ++g) {
            unsigned long long a0 = 0ull, a1 = 0ull;   // 2x f32x2 accumulators
#pragma unroll
            for (int i = 0; i < 8; ++i) {
                a0 = fma2(wreg[g][i].x, hreg[i].x, a0);
                a1 = fma2(wreg[g][i].y, hreg[i].y, a1);
            }
            float lo0, hi0, lo1, hi1;
            asm("mov.b64 {%0,%1}, %2;" : "=f"(lo0), "=f"(hi0) : "l"(a0));
            asm("mov.b64 {%0,%1}, %2;" : "=f"(lo1), "=f"(hi1) : "l"(a1));
            float s = (lo0 + hi0) + (lo1 + hi1);
#pragma unroll
            for (int o = 16; o; o >>= 1) s += __shfl_xor_sync(0xffffffffu, s, o);
            gate[g] = s;                     // every lane holds the sum
        }

        // lanes 0-3 each evaluate one activation
        float a = 0.f;
        if (lane < 4) {
            float pre = xgv + (lane == 0 ? gate[0] : lane == 1 ? gate[1]
                               : lane == 2 ? gate[2] : gate[3]);
            if (lane == 2) {
                a = 1.f - __fdividef(2.f, __expf(2.f * pre) + 1.f);  // tanh
            } else {
                a = __fdividef(1.f, 1.f + __expf(-pre));             // sigmoid
            }
        }
        float i_ = __shfl_sync(0xffffffffu, a, 0);
        float f_ = __shfl_sync(0xffffffffu, a, 1);
        float g_ = __shfl_sync(0xffffffffu, a, 2);
        float o_ = __shfl_sync(0xffffffffu, a, 3);

        float h_ = 0.f;
        if (lane == 0) {
            c_reg = f_ * c_reg + i_ * g_;
            float tc = 1.f - __fdividef(2.f, __expf(2.f * c_reg) + 1.f);
            h_ = o_ * tc;
            g_hbuf[(t + 1) & 1][j] = h_;     // critical-path store
        }
        float h_b = __shfl_sync(0xffffffffu, h_, 0);

        if (t < TT - 1) {
            __threadfence();                 // publish h writes (R2/R10-proven)
            __syncthreads();                 // whole CTA done with step t
            if (lane == 1)                   // bookkeeping off tid0's path
                g_hs16[(size_t)t * HH + j] = __float2bfloat16(h_b);
            if (tid == 0) {
                unsigned target = relbase + (unsigned)t + 1u;
                unsigned aold = atomicAdd(&g_arrive, 1u);
                if ((aold + 1u) % (unsigned)NCTA == 0u) {
                    atomicAdd(&g_release, 1u);   // last arriver releases all
                } else {
                    while ((int)(*(volatile unsigned*)&g_release - target) < 0) { }
                }
            }
            __syncthreads();
        } else {
            if (lane == 1)
                g_hs16[(size_t)t * HH + j] = __float2bfloat16(h_b);
            if (lane == 0) { out_tail[j] = h_; out_tail[HH + j] = c_reg; }
        }
    }
}

// =================================================================
// Row log-softmax — online max/sum in ONE read pass, then write pass.
// =================================================================
__global__ void __launch_bounds__(256) logsoftmax_kernel(
    const float* __restrict__ scores, float* __restrict__ out)
{
    __shared__ float mred[256];
    __shared__ float sred[256];
    const int row = blockIdx.x;
    const int tid = threadIdx.x;
    const float* s = scores + (size_t)row * VV;

    float m = -3.402823466e38f, su = 0.f;
    for (int v = tid; v < VV; v += 256) {
        float x = s[v];
        if (x > m) { su *= __expf(m - x); m = x; }
        su += __expf(x - m);
    }
    mred[tid] = m; sred[tid] = su; __syncthreads();
    for (int st = 128; st > 0; st >>= 1) {
        if (tid < st) {
            float m2 = mred[tid + st], s2 = sred[tid + st];
            float m1 = mred[tid],      s1 = sred[tid];
            float mn = fmaxf(m1, m2);
            sred[tid] = s1 * __expf(m1 - mn) + s2 * __expf(m2 - mn);
            mred[tid] = mn;
        }
        __syncthreads();
    }
    const float L = mred[0] + logf(sred[0]);

    float* o = out + (size_t)row * VV;
    for (int v = tid; v < VV; v += 256) o[v] = s[v] - L;
}

// =================================================================
extern "C" void kernel_launch(void* const* d_in, const int* in_sizes, int n_in,
                              void* d_out, int out_size)
{
    (void)in_sizes; (void)n_in; (void)out_size;
    const int*   seq   = (const int*)  d_in[0];
    const float* h0    = (const float*)d_in[1];
    const float* c0    = (const float*)d_in[2];
    const float* emb   = (const float*)d_in[3];
    const float* W_ih  = (const float*)d_in[4];
    const float* W_hh  = (const float*)d_in[5];
    const float* b_ih  = (const float*)d_in[6];
    const float* b_hh  = (const float*)d_in[7];
    const float* W_out = (const float*)d_in[8];
    const float* b_out = (const float*)d_in[9];
    float* out = (float*)d_out;

    float *p_xg = nullptr, *p_scores = nullptr;
    __nv_bfloat16 *p_x16 = nullptr, *p_wih16 = nullptr, *p_wout16 = nullptr,
                  *p_hs16 = nullptr;
    cudaGetSymbolAddress((void**)&p_xg, g_xg);
    cudaGetSymbolAddress((void**)&p_scores, g_scores);
    cudaGetSymbolAddress((void**)&p_x16, g_x16);
    cudaGetSymbolAddress((void**)&p_wih16, g_wih16);
    cudaGetSymbolAddress((void**)&p_wout16, g_wout16);
    cudaGetSymbolAddress((void**)&p_hs16, g_hs16);

    // allow 61.4 KB dynamic smem for the pipelined GEMM
    cudaFuncSetAttribute(bgemm_tn, cudaFuncAttributeMaxDynamicSharedMemorySize,
                         BGEMM_SMEM);

    // conversions (vectorized)
    gather_x16_kernel<<<TT, 256>>>(seq, emb);
    f2bf4_kernel<<<512, 256>>>((const float4*)W_ih, (uint2*)p_wih16,
                               (size_t)G4 * EE / 4);
    f2bf4_kernel<<<2048, 256>>>((const float4*)W_out, (uint2*)p_wout16,
                                (size_t)VV * HH / 4);

    // 1) xg = x @ W_ih^T + (b_ih + b_hh)   [T, 4H]
    {
        dim3 grid(G4 / 128, TT / 128);
        bgemm_tn<<<grid, 256, BGEMM_SMEM>>>(p_x16, p_wih16, b_ih, b_hh, p_xg,
                                            TT, G4, EE);
    }
    // 2) sequential LSTM scan
    lstm_scan_kernel<<<NCTA, 256>>>(h0, c0, W_hh, out + (size_t)TT * VV);
    // 3) scores = hs @ W_out^T + b_out     [T, V]
    {
        dim3 grid(VV / 128, TT / 128);
        bgemm_tn<<<grid, 256, BGEMM_SMEM>>>(p_hs16, p_wout16, b_out, nullptr,
                                            p_scores, TT, VV, HH);
    }
    // 4) logp = log_softmax(scores) -> d_out
    logsoftmax_kernel<<<TT, 256>>>(p_scores, out);
}